// round 10
// baseline (speedup 1.0000x reference)
#include <cuda_runtime.h>

#define GN 512
#define TBR 64          // tile rows
#define TBC 32          // tile cols
#define TD 8            // max temporal depth per launch
#define ROWS_HP 50      // padded rows per half (48 local + ring)
#define COLS_P 56       // float stride (conflict-free LDS.128 for 2-row strips)
#define NGRP 12         // 4-column groups (48 region cols)
#define NHALF 288       // threads per half = 12 groups x 24 two-row strips (9 warps)
#define NT 576          // two halves
#define TOTAL_STEPS 199

typedef unsigned long long u64;

__device__ __forceinline__ u64 PK(float a, float b) {
    u64 r; asm("mov.b64 %0,{%1,%2};" : "=l"(r) : "f"(a), "f"(b)); return r;
}
__device__ __forceinline__ void UNPK(u64 v, float& a, float& b) {
    asm("mov.b64 {%0,%1},%2;" : "=f"(a), "=f"(b) : "l"(v));
}
__device__ __forceinline__ u64 ADD2(u64 a, u64 b) {
    u64 d; asm("add.rn.f32x2 %0,%1,%2;" : "=l"(d) : "l"(a), "l"(b)); return d;
}
__device__ __forceinline__ u64 MUL2(u64 a, u64 b) {
    u64 d; asm("mul.rn.f32x2 %0,%1,%2;" : "=l"(d) : "l"(a), "l"(b)); return d;
}
__device__ __forceinline__ u64 FMA2(u64 a, u64 b, u64 c) {
    u64 d; asm("fma.rn.f32x2 %0,%1,%2,%3;" : "=l"(d) : "l"(a), "l"(b), "l"(c)); return d;
}
#define NBAR(id) asm volatile("bar.sync %0, %1;" :: "r"(id), "r"(NHALF) : "memory")

// new(i,j) = V(clamp(i,1,510), clamp(j,1,510)); state extended by clamp(.,0,511).
// 64x32 tiles -> 128 CTAs (one per SM). Each CTA is split into TWO independent
// sub-CTAs on overlapping row-halves of the 80x48 region (local rows = region
// 0..47 and 32..79; the 16-row overlap = 2*TD keeps them dependency-free for 8
// steps). Each half: private smem ping-pong + its own named barrier -> the two
// 9-warp groups drift in phase and hide each other's barrier-drain / LDS-ramp
// stalls on the same SMSPs. Step 0 fused with the global load (clamped LDG =
// true extended state; garbage ring starts eroding only at step 1); last step
// skips STS+barrier. Column specials branchless; row copies are same-thread
// overwrites (half A ty==4 owns global rows 0,1; half B ty==19 owns 510,511).
template <int NSTEPS>
__global__ __launch_bounds__(NT) void adr_chunk(
    const float* __restrict__ in_state,
    float* __restrict__ frames,
    const float* __restrict__ k1p, const float* __restrict__ k2p,
    const float* __restrict__ a1p, const float* __restrict__ a2p)
{
    __shared__ __align__(16) float buf[2][2][ROWS_HP][COLS_P];  // [half][pp]

    const float k1 = __ldg(k1p), k2 = __ldg(k2p);
    const float a1 = __ldg(a1p), a2 = __ldg(a2p);
    const float inv_k12 = 1.0f / (k1 + k2);
    const float inv_dx2 = 511.0f * 511.0f;
    const float inv_2dx = 255.5f;
    const float DTC = 1e-7f;

    const int by = blockIdx.y, bx = blockIdx.x;
    const int r0 = by * TBR - TD;
    const int c0 = bx * TBC - TD;
    const int tid  = (int)threadIdx.x;
    const int half = (tid >= NHALF) ? 1 : 0;
    const int ltid = tid - half * NHALF;
    const int g  = ltid % NGRP;                // 4-col group 0..11
    const int ty = ltid / NGRP;                // strip 0..23 (2 local rows)
    const int rbase = ty * 2;                  // local row of strip start
    const int hb = half ? 32 : 0;              // half's region-row offset
    const int barid = half + 1;                // named barrier 1 / 2
    const int gj0 = c0 + 4 * g;
    const int sc  = 4 * g + 4;                 // smem col (16B aligned)

    const float kap = (gj0 < 256) ? k1 : k2;   // 4 | 256: never straddles
    const float al  = (gj0 < 256) ? a1 : a2;

    const float A1c = DTC * al * inv_dx2;
    const u64 cA1   = PK(A1c, A1c);
    const u64 cM4A1 = PK(-4.0f * A1c, -4.0f * A1c);
    const u64 cM1   = PK(-1.0f, -1.0f);
    const u64 cONE  = PK(1.0f, 1.0f);
    const u64 cI2   = PK(inv_2dx, inv_2dx);
    const u64 cMI2  = PK(-inv_2dx, -inv_2dx);
    const u64 cB1   = PK(DTC * kap, DTC * kap);

    const bool colC = (g >= 2) && (g <= 9);            // central 32 cols
    const bool rowC = (ty >= 4) && (ty <= 19);         // local rows 8..39 central
    const bool storeC = colC && rowC;
    const bool isI  = (gj0 == 252);
    const bool isL  = (gj0 == 0);
    const bool isR  = (gj0 == 508);
    const bool topFix = (by == 0) && (half == 0) && (ty == 4);              // global rows 0,1
    const bool botFix = (by == GN / TBR - 1) && (half == 1) && (ty == 19);  // global rows 510,511

    auto pointPair = [&](u64 Tm, u64 Tc, u64 Tp, u64 L, u64 R) -> u64 {
        u64 sum  = ADD2(ADD2(Tm, Tp), ADD2(L, R));
        u64 lapc = FMA2(Tc, cM4A1, MUL2(sum, cA1));   // DT*al*lap
        u64 dxv  = FMA2(Tm, cM1, Tp);                  // Tp - Tm
        u64 dyv  = FMA2(L,  cM1, R);                   // R - L
        u64 P    = FMA2(dxv, cMI2, ADD2(Tc, cM1));     // (c-1) - T_x
        u64 Q    = FMA2(dyv, cI2,  cONE);              // T_y + 1
        u64 S    = FMA2(MUL2(Tc, Tc), P, MUL2(Tc, Q)); // c^2*P + c*Q
        return ADD2(Tc, FMA2(S, cB1, lapc));
    };

    auto rowcalc = [&](float4 Fm, float4 Fc, float4 Fp, float TlS, float TrS,
                       u64& v0, u64& v1) {
        u64 Tm0 = PK(Fm.x, Fm.y), Tc0 = PK(Fc.x, Fc.y), Tp0 = PK(Fp.x, Fp.y);
        u64 Tm1 = PK(Fm.z, Fm.w), Tc1 = PK(Fc.z, Fc.w), Tp1 = PK(Fp.z, Fp.w);
        u64 L0 = PK(TlS, Fc.x);
        u64 M  = PK(Fc.y, Fc.z);      // R of pair0 == L of pair1
        u64 R1 = PK(Fc.w, TrS);
        v0 = pointPair(Tm0, Tc0, Tp0, L0, M);
        v1 = pointPair(Tm1, Tc1, Tp1, M, R1);
        float a, b;
        UNPK(v1, a, b);
        float ifv = fmaf(k1, TrS, k2 * Fc.z) * inv_k12;  // interface col 255
        b = isI ? ifv : b;
        b = isR ? a : b;                                  // col 511 := 510
        v1 = PK(a, b);
        UNPK(v0, a, b);
        a = isL ? b : a;                                  // col 0 := 1
        v0 = PK(a, b);
    };

    auto F4 = [](u64 v0, u64 v1) -> float4 {
        float a, b, c, d; UNPK(v0, a, b); UNPK(v1, c, d);
        return make_float4(a, b, c, d);
    };

    float* const fr0 = frames + (ptrdiff_t)(r0 + hb + rbase) * GN + gj0;

    // ================= fused global load + STEP 0 =================
    {
        const bool canVec = (gj0 >= 0) && (gj0 + 3 < GN);
        const int j0 = min(max(gj0 + 0, 0), GN - 1);
        const int j1 = min(max(gj0 + 1, 0), GN - 1);
        const int j2 = min(max(gj0 + 2, 0), GN - 1);
        const int j3 = min(max(gj0 + 3, 0), GN - 1);
        const int jl = min(max(gj0 - 1, 0), GN - 1);
        const int jr = min(max(gj0 + 4, 0), GN - 1);

        auto ldrow = [&](int gi) -> float4 {
            int li = min(max(gi, 0), GN - 1);
            if (canVec) return *(const float4*)&in_state[(size_t)li * GN + gj0];
            return make_float4(in_state[(size_t)li * GN + j0],
                               in_state[(size_t)li * GN + j1],
                               in_state[(size_t)li * GN + j2],
                               in_state[(size_t)li * GN + j3]);
        };
        auto lded = [&](int gi, int jj) -> float {
            int li = min(max(gi, 0), GN - 1);
            return in_state[(size_t)li * GN + jj];
        };

        const int gr = r0 + hb + rbase;      // global row of strip start
        float4 Fm = ldrow(gr - 1);
        float4 F1 = ldrow(gr);
        float4 F2 = ldrow(gr + 1);
        float4 F3 = ldrow(gr + 2);
        float TlA = lded(gr,     jl), TrA = lded(gr,     jr);
        float TlB = lded(gr + 1, jl), TrB = lded(gr + 1, jr);

        u64 a0, a1v, b0, b1v;
        rowcalc(Fm, F1, F2, TlA, TrA, a0, a1v);
        rowcalc(F1, F2, F3, TlB, TrB, b0, b1v);
        float4 VA = F4(a0, a1v);
        float4 VB = F4(b0, b1v);

        *(float4*)&buf[half][0][rbase + 1][sc] = VA;
        *(float4*)&buf[half][0][rbase + 2][sc] = VB;
        if (storeC) {
            *(float4*)&fr0[0]  = VA;
            *(float4*)&fr0[GN] = VB;
        }
        if (topFix) {               // global row 0 := row 1
            *(float4*)&buf[0][0][9][sc] = VB;      // local row 8
            if (colC) *(float4*)&frames[gj0] = VB;
        }
        if (botFix) {               // global row 511 := row 510
            *(float4*)&buf[1][0][40][sc] = VA;     // local row 39
            if (colC) *(float4*)&frames[(size_t)(GN - 1) * GN + gj0] = VA;
        }
    }
    NBAR(barid);

    // ================= steps 1 .. NSTEPS-1 (per-half smem ping-pong) =================
    #pragma unroll
    for (int s = 1; s < NSTEPS; ++s) {
        const float (*A)[COLS_P] = buf[half][(s + 1) & 1];
        float (*B)[COLS_P] = buf[half][s & 1];
        float* f0 = fr0 + (size_t)s * (GN * GN);
        const bool last = (s == NSTEPS - 1);

        float4 F0 = *(const float4*)&A[rbase + 0][sc];
        float4 F1 = *(const float4*)&A[rbase + 1][sc];
        float4 F2 = *(const float4*)&A[rbase + 2][sc];
        float4 F3 = *(const float4*)&A[rbase + 3][sc];
        float TlA = A[rbase + 1][sc - 1], TrA = A[rbase + 1][sc + 4];
        float TlB = A[rbase + 2][sc - 1], TrB = A[rbase + 2][sc + 4];

        u64 a0, a1v, b0, b1v;
        rowcalc(F0, F1, F2, TlA, TrA, a0, a1v);
        rowcalc(F1, F2, F3, TlB, TrB, b0, b1v);
        float4 VA = F4(a0, a1v);
        float4 VB = F4(b0, b1v);

        if (!last) {
            *(float4*)&B[rbase + 1][sc] = VA;
            *(float4*)&B[rbase + 2][sc] = VB;
        }
        if (storeC) {
            *(float4*)&f0[0]  = VA;
            *(float4*)&f0[GN] = VB;
        }
        if (topFix) {               // global row 0 := row 1
            if (!last) *(float4*)&B[9][sc] = VB;
            if (colC) *(float4*)&frames[(size_t)s * (GN * GN) + gj0] = VB;
        }
        if (botFix) {               // global row 511 := row 510
            if (!last) *(float4*)&B[40][sc] = VA;
            if (colC) *(float4*)&frames[(size_t)s * (GN * GN) + (size_t)(GN - 1) * GN + gj0] = VA;
        }
        if (!last) NBAR(barid);
    }
}

extern "C" void kernel_launch(void* const* d_in, const int* in_sizes, int n_in,
                              void* d_out, int out_size)
{
    (void)in_sizes; (void)n_in; (void)out_size;
    const float* u0 = (const float*)d_in[0];
    const float* k1 = (const float*)d_in[1];
    const float* k2 = (const float*)d_in[2];
    const float* a1 = (const float*)d_in[3];
    const float* a2 = (const float*)d_in[4];
    float* out = (float*)d_out;

    dim3 grid(GN / TBC, GN / TBR);   // 16 x 8 = 128 CTAs
    dim3 block(NT);

    int done = 0;
    const float* src = u0;
    while (done < TOTAL_STEPS) {
        int steps = TOTAL_STEPS - done;
        if (steps >= TD) {
            adr_chunk<TD><<<grid, block>>>(src, out + (size_t)done * GN * GN,
                                           k1, k2, a1, a2);
            steps = TD;
        } else {
            adr_chunk<TD - 1><<<grid, block>>>(src, out + (size_t)done * GN * GN,
                                               k1, k2, a1, a2);  // final 7-step chunk
        }
        src = out + (size_t)(done + steps - 1) * GN * GN;
        done += steps;
    }
}

// round 11
// speedup vs baseline: 1.1249x; 1.1249x over previous
#include <cuda_runtime.h>
#include <cstring>

#define GN 512
#define TBR 64          // tile rows
#define TBC 32          // tile cols
#define TD 8            // max temporal depth per launch
#define ROWS_P 82       // padded smem rows (region 80 + ring)
#define COLS_P 56       // float stride: 2-row offset 112 = 16 mod 32 -> conflict-free LDS.128
#define NGRP 12         // 4-column groups per region (48 cols)
#define NT 480          // 12 groups x 40 two-row strips
#define TOTAL_STEPS 199

typedef unsigned long long u64;
typedef ulonglong2 V4;      // one smem row quad: .x = cols(0,1) packed, .y = cols(2,3)

__device__ __forceinline__ u64 PKf(float a, float b) {
    float2 t = make_float2(a, b); u64 r; memcpy(&r, &t, 8); return r;
}
__device__ __forceinline__ float2 UPf(u64 v) {
    float2 t; memcpy(&t, &v, 8); return t;
}
__device__ __forceinline__ u64 ADD2(u64 a, u64 b) {
    u64 d; asm("add.rn.f32x2 %0,%1,%2;" : "=l"(d) : "l"(a), "l"(b)); return d;
}
__device__ __forceinline__ u64 MUL2(u64 a, u64 b) {
    u64 d; asm("mul.rn.f32x2 %0,%1,%2;" : "=l"(d) : "l"(a), "l"(b)); return d;
}
__device__ __forceinline__ u64 FMA2(u64 a, u64 b, u64 c) {
    u64 d; asm("fma.rn.f32x2 %0,%1,%2,%3;" : "=l"(d) : "l"(a), "l"(b), "l"(c)); return d;
}

// new(i,j) = V(clamp(i,1,510), clamp(j,1,510)); state extended by clamp(.,0,511).
// 64x32 tiles -> 128 CTAs (one per SM). Thread = 4-col group x 2-row strip; full
// 80x48 region recomputed per step in a garbage-ringed smem buffer (erosion 1
// cell/step; central 64x32 exact for 8 steps). Step 0 fused with the global load;
// last step skips STS+barrier. THIS ROUND: smem rows flow as ulonglong2 so the
// LDS.128 register pairs feed f32x2 math directly -- only the 3 horizontal
// vectors are packed, results store back as ulonglong2 (no unpack). One ADD2
// folded away via Tc*(1-4A1). Col specials branchless; row copies same-thread.
template <int NSTEPS>
__global__ __launch_bounds__(NT) void adr_chunk(
    const float* __restrict__ in_state,
    float* __restrict__ frames,
    const float* __restrict__ k1p, const float* __restrict__ k2p,
    const float* __restrict__ a1p, const float* __restrict__ a2p)
{
    __shared__ __align__(16) float buf[2][ROWS_P][COLS_P];

    const float k1 = __ldg(k1p), k2 = __ldg(k2p);
    const float a1 = __ldg(a1p), a2 = __ldg(a2p);
    const float inv_k12 = 1.0f / (k1 + k2);
    const float inv_dx2 = 511.0f * 511.0f;
    const float inv_2dx = 255.5f;
    const float DTC = 1e-7f;

    const int by = blockIdx.y, bx = blockIdx.x;
    const int r0 = by * TBR - TD;
    const int c0 = bx * TBC - TD;
    const int g  = (int)threadIdx.x % NGRP;    // 4-col group 0..11
    const int ty = (int)threadIdx.x / NGRP;    // strip 0..39 (2 rows)
    const int rbase = ty * 2;
    const int gj0 = c0 + 4 * g;
    const int sc  = 4 * g + 4;                 // smem col (16B aligned)

    const float kap = (gj0 < 256) ? k1 : k2;   // 4 | 256: never straddles
    const float al  = (gj0 < 256) ? a1 : a2;

    const float A1c = DTC * al * inv_dx2;
    const u64 cA1    = PKf(A1c, A1c);
    const u64 c1M4A1 = PKf(1.0f - 4.0f * A1c, 1.0f - 4.0f * A1c); // folds Tc + lap center
    const u64 cM1    = PKf(-1.0f, -1.0f);
    const u64 cONE   = PKf(1.0f, 1.0f);
    const u64 cI2    = PKf(inv_2dx, inv_2dx);
    const u64 cMI2   = PKf(-inv_2dx, -inv_2dx);
    const u64 cB1    = PKf(DTC * kap, DTC * kap);

    const bool colC = (g >= 2) && (g <= 9);            // central 32 cols
    const bool rowC = (ty >= 4) && (ty <= 35);         // central 64 rows
    const bool storeC = colC && rowC;
    const bool isI  = (gj0 == 252);                    // group holding col 255
    const bool isL  = (gj0 == 0);
    const bool isR  = (gj0 == 508);                    // group holding col 511
    const bool topFix = (by == 0) && (ty == 4);            // global rows 0,1
    const bool botFix = (by == GN / TBR - 1) && (ty == 35); // global rows 510,511

    // one column-pair update: Tn = Tc(1-4A1) + A1*sum + B1*(Tc^2*P + Tc*Q)
    auto pointPair = [&](u64 Tm, u64 Tc, u64 Tp, u64 L, u64 R) -> u64 {
        u64 sum  = ADD2(ADD2(Tm, Tp), ADD2(L, R));
        u64 lapc = FMA2(Tc, c1M4A1, MUL2(sum, cA1));   // Tc + DT*al*lap
        u64 dxv  = FMA2(Tm, cM1, Tp);                   // Tp - Tm
        u64 dyv  = FMA2(L,  cM1, R);                    // R - L
        u64 P    = FMA2(dxv, cMI2, ADD2(Tc, cM1));      // (c-1) - T_x
        u64 Q    = FMA2(dyv, cI2,  cONE);               // T_y + 1
        u64 S    = FMA2(MUL2(Tc, Tc), P, MUL2(Tc, Q));  // c^2*P + c*Q
        return FMA2(S, cB1, lapc);
    };

    // full 4-col row: LDS.128 pairs feed f32x2 math directly
    auto rowcalc = [&](V4 Fm, V4 Fc, V4 Fp, float TlS, float TrS) -> V4 {
        float2 cl = UPf(Fc.x);                 // cols 0,1 of group
        float2 ch = UPf(Fc.y);                 // cols 2,3
        u64 L0 = PKf(TlS, cl.x);
        u64 M  = PKf(cl.y, ch.x);              // R of pair0 == L of pair1
        u64 R1 = PKf(ch.y, TrS);
        u64 v0 = pointPair(Fm.x, Fc.x, Fp.x, L0, M);
        u64 v1 = pointPair(Fm.y, Fc.y, Fp.y, M, R1);
        float2 vh = UPf(v1);
        float ifv = fmaf(k1, TrS, k2 * ch.x) * inv_k12;  // interface col 255
        vh.y = isI ? ifv : vh.y;
        vh.y = isR ? vh.x : vh.y;                         // col 511 := 510
        v1 = PKf(vh.x, vh.y);
        float2 vl = UPf(v0);
        vl.x = isL ? vl.y : vl.x;                         // col 0 := 1
        v0 = PKf(vl.x, vl.y);
        V4 out; out.x = v0; out.y = v1; return out;
    };

    float* const fr0 = frames + (ptrdiff_t)(r0 + rbase) * GN + gj0;

    // ================= fused global load + STEP 0 =================
    {
        const bool canVec = (gj0 >= 0) && (gj0 + 3 < GN);
        const int j0 = min(max(gj0 + 0, 0), GN - 1);
        const int j1 = min(max(gj0 + 1, 0), GN - 1);
        const int j2 = min(max(gj0 + 2, 0), GN - 1);
        const int j3 = min(max(gj0 + 3, 0), GN - 1);
        const int jl = min(max(gj0 - 1, 0), GN - 1);
        const int jr = min(max(gj0 + 4, 0), GN - 1);

        auto ldrow = [&](int gi) -> V4 {
            int li = min(max(gi, 0), GN - 1);
            if (canVec) return *(const V4*)&in_state[(size_t)li * GN + gj0];
            V4 v;
            v.x = PKf(in_state[(size_t)li * GN + j0], in_state[(size_t)li * GN + j1]);
            v.y = PKf(in_state[(size_t)li * GN + j2], in_state[(size_t)li * GN + j3]);
            return v;
        };
        auto lded = [&](int gi, int jj) -> float {
            int li = min(max(gi, 0), GN - 1);
            return in_state[(size_t)li * GN + jj];
        };

        V4 Fm = ldrow(r0 + rbase - 1);
        V4 F1 = ldrow(r0 + rbase);
        V4 F2 = ldrow(r0 + rbase + 1);
        V4 F3 = ldrow(r0 + rbase + 2);
        float TlA = lded(r0 + rbase,     jl), TrA = lded(r0 + rbase,     jr);
        float TlB = lded(r0 + rbase + 1, jl), TrB = lded(r0 + rbase + 1, jr);

        V4 VA = rowcalc(Fm, F1, F2, TlA, TrA);   // region row rbase
        V4 VB = rowcalc(F1, F2, F3, TlB, TrB);   // region row rbase+1

        *(V4*)&buf[0][rbase + 1][sc] = VA;
        *(V4*)&buf[0][rbase + 2][sc] = VB;
        if (storeC) {
            *(V4*)&fr0[0]  = VA;
            *(V4*)&fr0[GN] = VB;
        }
        if (topFix) {               // global row 0 := row 1
            *(V4*)&buf[0][9][sc] = VB;
            if (colC) *(V4*)&frames[gj0] = VB;
        }
        if (botFix) {               // global row 511 := row 510
            *(V4*)&buf[0][72][sc] = VA;
            if (colC) *(V4*)&frames[(size_t)(GN - 1) * GN + gj0] = VA;
        }
    }
    __syncthreads();

    // ================= steps 1 .. NSTEPS-1 (smem ping-pong) =================
    #pragma unroll
    for (int s = 1; s < NSTEPS; ++s) {
        const float (*A)[COLS_P] = buf[(s + 1) & 1];
        float (*B)[COLS_P] = buf[s & 1];
        float* f0 = fr0 + (size_t)s * (GN * GN);
        const bool last = (s == NSTEPS - 1);

        V4 F0 = *(const V4*)&A[rbase + 0][sc];
        V4 F1 = *(const V4*)&A[rbase + 1][sc];
        V4 F2 = *(const V4*)&A[rbase + 2][sc];
        V4 F3 = *(const V4*)&A[rbase + 3][sc];
        float TlA = A[rbase + 1][sc - 1], TrA = A[rbase + 1][sc + 4];
        float TlB = A[rbase + 2][sc - 1], TrB = A[rbase + 2][sc + 4];

        V4 VA = rowcalc(F0, F1, F2, TlA, TrA);   // region row rbase
        V4 VB = rowcalc(F1, F2, F3, TlB, TrB);   // region row rbase+1

        if (!last) {
            *(V4*)&B[rbase + 1][sc] = VA;
            *(V4*)&B[rbase + 2][sc] = VB;
        }
        if (storeC) {
            *(V4*)&f0[0]  = VA;
            *(V4*)&f0[GN] = VB;
        }
        if (topFix) {               // global row 0 := row 1
            if (!last) *(V4*)&B[9][sc] = VB;
            if (colC) *(V4*)&frames[(size_t)s * (GN * GN) + gj0] = VB;
        }
        if (botFix) {               // global row 511 := row 510
            if (!last) *(V4*)&B[72][sc] = VA;
            if (colC) *(V4*)&frames[(size_t)s * (GN * GN) + (size_t)(GN - 1) * GN + gj0] = VA;
        }
        if (!last) __syncthreads();
    }
}

extern "C" void kernel_launch(void* const* d_in, const int* in_sizes, int n_in,
                              void* d_out, int out_size)
{
    (void)in_sizes; (void)n_in; (void)out_size;
    const float* u0 = (const float*)d_in[0];
    const float* k1 = (const float*)d_in[1];
    const float* k2 = (const float*)d_in[2];
    const float* a1 = (const float*)d_in[3];
    const float* a2 = (const float*)d_in[4];
    float* out = (float*)d_out;

    dim3 grid(GN / TBC, GN / TBR);   // 16 x 8 = 128 CTAs
    dim3 block(NT);

    int done = 0;
    const float* src = u0;
    while (done < TOTAL_STEPS) {
        int steps = TOTAL_STEPS - done;
        if (steps >= TD) {
            adr_chunk<TD><<<grid, block>>>(src, out + (size_t)done * GN * GN,
                                           k1, k2, a1, a2);
            steps = TD;
        } else {
            adr_chunk<TD - 1><<<grid, block>>>(src, out + (size_t)done * GN * GN,
                                               k1, k2, a1, a2);  // final 7-step chunk
        }
        src = out + (size_t)(done + steps - 1) * GN * GN;
        done += steps;
    }
}

// round 12
// speedup vs baseline: 1.3087x; 1.1634x over previous
#include <cuda_runtime.h>
#include <cstring>

#define GN 512
#define TBR 64          // tile rows
#define TBC 32          // tile cols
#define TD 8            // max temporal depth per launch
#define ROWS_P 82       // padded smem rows (region 80 + ring)
#define COLS_P 56       // float stride: 2-row offset 112 = 16 mod 32 -> conflict-free LDS.128
#define NGRP 12         // 4-column groups per region (48 cols)
#define NT 480          // 12 groups x 40 two-row strips
#define TOTAL_STEPS 199

typedef unsigned long long u64;
typedef ulonglong2 V4;      // one smem row quad: .x = cols(0,1) packed, .y = cols(2,3)

__device__ __forceinline__ u64 PKf(float a, float b) {
    float2 t = make_float2(a, b); u64 r; memcpy(&r, &t, 8); return r;
}
__device__ __forceinline__ float2 UPf(u64 v) {
    float2 t; memcpy(&t, &v, 8); return t;
}
__device__ __forceinline__ u64 ADD2(u64 a, u64 b) {
    u64 d; asm("add.rn.f32x2 %0,%1,%2;" : "=l"(d) : "l"(a), "l"(b)); return d;
}
__device__ __forceinline__ u64 MUL2(u64 a, u64 b) {
    u64 d; asm("mul.rn.f32x2 %0,%1,%2;" : "=l"(d) : "l"(a), "l"(b)); return d;
}
__device__ __forceinline__ u64 FMA2(u64 a, u64 b, u64 c) {
    u64 d; asm("fma.rn.f32x2 %0,%1,%2,%3;" : "=l"(d) : "l"(a), "l"(b), "l"(c)); return d;
}

// new(i,j) = V(clamp(i,1,510), clamp(j,1,510)); state extended by clamp(.,0,511).
// 64x32 tiles -> 128 CTAs (one per SM). Thread = 4-col group x 2-row strip; full
// 80x48 region recomputed per step in a garbage-ringed smem buffer (erosion 1
// cell/step; central 64x32 exact for 8 steps). Step 0 fused with the global load;
// last step skips STS+barrier. smem rows flow as ulonglong2 (LDS.128 pairs feed
// f32x2 math directly). THIS ROUND: PDL — each chunk launches with programmatic
// stream serialization; the whole preamble (indices, constants, flags) runs
// BEFORE cudaGridDependencySynchronize(), so successor CTAs ramp up while the
// predecessor drains. Only the step-0 reads of the previous chunk's final frame
// sit after the fence.
template <int NSTEPS>
__global__ __launch_bounds__(NT) void adr_chunk(
    const float* __restrict__ in_state,
    float* __restrict__ frames,
    const float* __restrict__ k1p, const float* __restrict__ k2p,
    const float* __restrict__ a1p, const float* __restrict__ a2p)
{
    __shared__ __align__(16) float buf[2][ROWS_P][COLS_P];

    // ---------- preamble: safe before the PDL fence ----------
    const float k1 = __ldg(k1p), k2 = __ldg(k2p);   // harness inputs, not produced
    const float a1 = __ldg(a1p), a2 = __ldg(a2p);   // by the predecessor kernel
    const float inv_k12 = 1.0f / (k1 + k2);
    const float inv_dx2 = 511.0f * 511.0f;
    const float inv_2dx = 255.5f;
    const float DTC = 1e-7f;

    const int by = blockIdx.y, bx = blockIdx.x;
    const int r0 = by * TBR - TD;
    const int c0 = bx * TBC - TD;
    const int g  = (int)threadIdx.x % NGRP;    // 4-col group 0..11
    const int ty = (int)threadIdx.x / NGRP;    // strip 0..39 (2 rows)
    const int rbase = ty * 2;
    const int gj0 = c0 + 4 * g;
    const int sc  = 4 * g + 4;                 // smem col (16B aligned)

    const float kap = (gj0 < 256) ? k1 : k2;   // 4 | 256: never straddles
    const float al  = (gj0 < 256) ? a1 : a2;

    const float A1c = DTC * al * inv_dx2;
    const u64 cA1    = PKf(A1c, A1c);
    const u64 c1M4A1 = PKf(1.0f - 4.0f * A1c, 1.0f - 4.0f * A1c);
    const u64 cM1    = PKf(-1.0f, -1.0f);
    const u64 cONE   = PKf(1.0f, 1.0f);
    const u64 cI2    = PKf(inv_2dx, inv_2dx);
    const u64 cMI2   = PKf(-inv_2dx, -inv_2dx);
    const u64 cB1    = PKf(DTC * kap, DTC * kap);

    const bool colC = (g >= 2) && (g <= 9);            // central 32 cols
    const bool rowC = (ty >= 4) && (ty <= 35);         // central 64 rows
    const bool storeC = colC && rowC;
    const bool isI  = (gj0 == 252);                    // group holding col 255
    const bool isL  = (gj0 == 0);
    const bool isR  = (gj0 == 508);                    // group holding col 511
    const bool topFix = (by == 0) && (ty == 4);            // global rows 0,1
    const bool botFix = (by == GN / TBR - 1) && (ty == 35); // global rows 510,511

    auto pointPair = [&](u64 Tm, u64 Tc, u64 Tp, u64 L, u64 R) -> u64 {
        u64 sum  = ADD2(ADD2(Tm, Tp), ADD2(L, R));
        u64 lapc = FMA2(Tc, c1M4A1, MUL2(sum, cA1));   // Tc + DT*al*lap
        u64 dxv  = FMA2(Tm, cM1, Tp);                   // Tp - Tm
        u64 dyv  = FMA2(L,  cM1, R);                    // R - L
        u64 P    = FMA2(dxv, cMI2, ADD2(Tc, cM1));      // (c-1) - T_x
        u64 Q    = FMA2(dyv, cI2,  cONE);               // T_y + 1
        u64 S    = FMA2(MUL2(Tc, Tc), P, MUL2(Tc, Q));  // c^2*P + c*Q
        return FMA2(S, cB1, lapc);
    };

    auto rowcalc = [&](V4 Fm, V4 Fc, V4 Fp, float TlS, float TrS) -> V4 {
        float2 cl = UPf(Fc.x);
        float2 ch = UPf(Fc.y);
        u64 L0 = PKf(TlS, cl.x);
        u64 M  = PKf(cl.y, ch.x);              // R of pair0 == L of pair1
        u64 R1 = PKf(ch.y, TrS);
        u64 v0 = pointPair(Fm.x, Fc.x, Fp.x, L0, M);
        u64 v1 = pointPair(Fm.y, Fc.y, Fp.y, M, R1);
        float2 vh = UPf(v1);
        float ifv = fmaf(k1, TrS, k2 * ch.x) * inv_k12;  // interface col 255
        vh.y = isI ? ifv : vh.y;
        vh.y = isR ? vh.x : vh.y;                         // col 511 := 510
        v1 = PKf(vh.x, vh.y);
        float2 vl = UPf(v0);
        vl.x = isL ? vl.y : vl.x;                         // col 0 := 1
        v0 = PKf(vl.x, vl.y);
        V4 out; out.x = v0; out.y = v1; return out;
    };

    float* const fr0 = frames + (ptrdiff_t)(r0 + rbase) * GN + gj0;

    const bool canVec = (gj0 >= 0) && (gj0 + 3 < GN);
    const int j0 = min(max(gj0 + 0, 0), GN - 1);
    const int j1 = min(max(gj0 + 1, 0), GN - 1);
    const int j2 = min(max(gj0 + 2, 0), GN - 1);
    const int j3 = min(max(gj0 + 3, 0), GN - 1);
    const int jl = min(max(gj0 - 1, 0), GN - 1);
    const int jr = min(max(gj0 + 4, 0), GN - 1);

    // ---------- PDL fence: predecessor's final frame must be visible ----------
#if __CUDA_ARCH__ >= 900
    cudaGridDependencySynchronize();
#endif

    // ================= fused global load + STEP 0 =================
    {
        auto ldrow = [&](int gi) -> V4 {
            int li = min(max(gi, 0), GN - 1);
            if (canVec) return *(const V4*)&in_state[(size_t)li * GN + gj0];
            V4 v;
            v.x = PKf(in_state[(size_t)li * GN + j0], in_state[(size_t)li * GN + j1]);
            v.y = PKf(in_state[(size_t)li * GN + j2], in_state[(size_t)li * GN + j3]);
            return v;
        };
        auto lded = [&](int gi, int jj) -> float {
            int li = min(max(gi, 0), GN - 1);
            return in_state[(size_t)li * GN + jj];
        };

        V4 Fm = ldrow(r0 + rbase - 1);
        V4 F1 = ldrow(r0 + rbase);
        V4 F2 = ldrow(r0 + rbase + 1);
        V4 F3 = ldrow(r0 + rbase + 2);
        float TlA = lded(r0 + rbase,     jl), TrA = lded(r0 + rbase,     jr);
        float TlB = lded(r0 + rbase + 1, jl), TrB = lded(r0 + rbase + 1, jr);

        V4 VA = rowcalc(Fm, F1, F2, TlA, TrA);
        V4 VB = rowcalc(F1, F2, F3, TlB, TrB);

        *(V4*)&buf[0][rbase + 1][sc] = VA;
        *(V4*)&buf[0][rbase + 2][sc] = VB;
        if (storeC) {
            *(V4*)&fr0[0]  = VA;
            *(V4*)&fr0[GN] = VB;
        }
        if (topFix) {               // global row 0 := row 1
            *(V4*)&buf[0][9][sc] = VB;
            if (colC) *(V4*)&frames[gj0] = VB;
        }
        if (botFix) {               // global row 511 := row 510
            *(V4*)&buf[0][72][sc] = VA;
            if (colC) *(V4*)&frames[(size_t)(GN - 1) * GN + gj0] = VA;
        }
    }
    __syncthreads();

    // ================= steps 1 .. NSTEPS-1 (smem ping-pong) =================
    #pragma unroll
    for (int s = 1; s < NSTEPS; ++s) {
        const float (*A)[COLS_P] = buf[(s + 1) & 1];
        float (*B)[COLS_P] = buf[s & 1];
        float* f0 = fr0 + (size_t)s * (GN * GN);
        const bool last = (s == NSTEPS - 1);

        V4 F0 = *(const V4*)&A[rbase + 0][sc];
        V4 F1 = *(const V4*)&A[rbase + 1][sc];
        V4 F2 = *(const V4*)&A[rbase + 2][sc];
        V4 F3 = *(const V4*)&A[rbase + 3][sc];
        float TlA = A[rbase + 1][sc - 1], TrA = A[rbase + 1][sc + 4];
        float TlB = A[rbase + 2][sc - 1], TrB = A[rbase + 2][sc + 4];

        V4 VA = rowcalc(F0, F1, F2, TlA, TrA);
        V4 VB = rowcalc(F1, F2, F3, TlB, TrB);

        if (!last) {
            *(V4*)&B[rbase + 1][sc] = VA;
            *(V4*)&B[rbase + 2][sc] = VB;
        }
        if (storeC) {
            *(V4*)&f0[0]  = VA;
            *(V4*)&f0[GN] = VB;
        }
        if (topFix) {               // global row 0 := row 1
            if (!last) *(V4*)&B[9][sc] = VB;
            if (colC) *(V4*)&frames[(size_t)s * (GN * GN) + gj0] = VB;
        }
        if (botFix) {               // global row 511 := row 510
            if (!last) *(V4*)&B[72][sc] = VA;
            if (colC) *(V4*)&frames[(size_t)s * (GN * GN) + (size_t)(GN - 1) * GN + gj0] = VA;
        }
        if (!last) __syncthreads();
    }

#if __CUDA_ARCH__ >= 900
    cudaTriggerProgrammaticLaunchCompletion();
#endif
}

static void launch_pdl(const void* func, const float* src, float* dst,
                       const float* k1, const float* k2,
                       const float* a1, const float* a2)
{
    cudaLaunchConfig_t cfg = {};
    cfg.gridDim  = dim3(GN / TBC, GN / TBR);   // 16 x 8 = 128 CTAs
    cfg.blockDim = dim3(NT);
    cfg.dynamicSmemBytes = 0;
    cfg.stream = 0;
    cudaLaunchAttribute attr[1];
    attr[0].id = cudaLaunchAttributeProgrammaticStreamSerialization;
    attr[0].val.programmaticStreamSerializationAllowed = 1;
    cfg.attrs = attr;
    cfg.numAttrs = 1;
    void* args[] = { (void*)&src, (void*)&dst, (void*)&k1, (void*)&k2,
                     (void*)&a1, (void*)&a2 };
    cudaLaunchKernelExC(&cfg, func, args);
}

extern "C" void kernel_launch(void* const* d_in, const int* in_sizes, int n_in,
                              void* d_out, int out_size)
{
    (void)in_sizes; (void)n_in; (void)out_size;
    const float* u0 = (const float*)d_in[0];
    const float* k1 = (const float*)d_in[1];
    const float* k2 = (const float*)d_in[2];
    const float* a1 = (const float*)d_in[3];
    const float* a2 = (const float*)d_in[4];
    float* out = (float*)d_out;

    int done = 0;
    const float* src = u0;
    while (done < TOTAL_STEPS) {
        int steps = TOTAL_STEPS - done;
        if (steps >= TD) {
            launch_pdl((const void*)adr_chunk<TD>, src,
                       out + (size_t)done * GN * GN, k1, k2, a1, a2);
            steps = TD;
        } else {
            launch_pdl((const void*)adr_chunk<TD - 1>, src,
                       out + (size_t)done * GN * GN, k1, k2, a1, a2);
        }
        src = out + (size_t)(done + steps - 1) * GN * GN;
        done += steps;
    }
}